// round 7
// baseline (speedup 1.0000x reference)
#include <cuda_runtime.h>
#include <cuda_fp16.h>
#include <math.h>

#define NUM_NODES 50000
#define DIM       64
#define DIM2      32            // half2 per feature row
#define ROWU4     8             // uint4 (16B) chunks per row (128 B row)
#define NUM_EDGES 800000
#define CAP       128           // bucket capacity per destination node
#define EPSN      1e-12f

// ---------------- scratch (static device globals; device-code refs only) ----------------
__device__ __half2  g_y0  [3][NUM_NODES * DIM2];   // dinv_k * l2norm(x), fp16
__device__ __half2  g_bufA[3][NUM_NODES * DIM2];   // layer-1 out (incl. dinv^2), fp16
__device__ float    g_bufB[3][NUM_NODES * DIM];    // layer-2 out (unscaled), fp32
__device__ int      g_cnt [3][NUM_NODES];          // degrees / append cursors
__device__ float    g_dinv[3][NUM_NODES];
__device__ unsigned short g_bkt[3][NUM_NODES * CAP]; // src indices per dst bucket

// ---------------- kernels ----------------

__global__ __launch_bounds__(256)
void zero3_kernel() {
    int i = blockIdx.x * blockDim.x + threadIdx.x;
    if (i < NUM_NODES) { g_cnt[0][i] = 0; g_cnt[1][i] = 0; g_cnt[2][i] = 0; }
}

// single-pass bucket scatter: degree counts AND per-dst edge lists
__global__ __launch_bounds__(256)
void bucket3_kernel(const int* __restrict__ ei0, const int* __restrict__ ei1,
                    const int* __restrict__ ei2) {
    int e = blockIdx.x * blockDim.x + threadIdx.x;
    if (e >= NUM_EDGES) return;
    int k = blockIdx.y;
    const int* ei = (k == 0) ? ei0 : (k == 1) ? ei1 : ei2;
    int s = ei[e];
    int d = ei[e + NUM_EDGES];
    int p = atomicAdd(&g_cnt[k][d], 1);
    if (p < CAP) g_bkt[k][(size_t)d * CAP + p] = (unsigned short)s;
}

// dinv_k = cnt>0 ? rsqrt(cnt) : 0 ; y0_k = half(dinv_k * x / max(||x||,eps))
__global__ __launch_bounds__(256)
void norm_scale3_kernel(const float* __restrict__ x) {
    int w    = (blockIdx.x * blockDim.x + threadIdx.x) >> 5;
    int lane = threadIdx.x & 31;
    if (w >= NUM_NODES) return;
    const float2 v = *reinterpret_cast<const float2*>(x + (size_t)w * DIM + lane * 2);
    float sq = v.x * v.x + v.y * v.y;
    #pragma unroll
    for (int o = 16; o; o >>= 1) sq += __shfl_xor_sync(0xffffffffu, sq, o);
    float s = 1.0f / fmaxf(sqrtf(sq), EPSN);
    #pragma unroll
    for (int k = 0; k < 3; k++) {
        int   c  = g_cnt[k][w];
        float dv = (c > 0) ? rsqrtf((float)c) : 0.0f;
        if (lane == 0) g_dinv[k][w] = dv;
        float sc = s * dv;
        g_y0[k][(size_t)w * DIM2 + lane] = __floats2half2_rn(v.x * sc, v.y * sc);
    }
}

__device__ __forceinline__ unsigned src_from_words(unsigned lo, unsigned hi, int g) {
    unsigned word = (g & 2) ? hi : lo;
    return (g & 1) ? (word >> 16) : (word & 0xFFFFu);
}

__device__ __forceinline__ void hacc(__half2 (&acc)[4], const uint4& v) {
    acc[0] = __hadd2(acc[0], *reinterpret_cast<const __half2*>(&v.x));
    acc[1] = __hadd2(acc[1], *reinterpret_cast<const __half2*>(&v.y));
    acc[2] = __hadd2(acc[2], *reinterpret_cast<const __half2*>(&v.z));
    acc[3] = __hadd2(acc[3], *reinterpret_cast<const __half2*>(&v.w));
}

// LGConv layer, all 3 relations (gridDim.y = 3); warp per destination node.
// Wide-lane gather: 4 groups x 8 lanes; group g = edge slot, lane i = 16B row chunk.
// LAYER=0: bufA = dinv[dst]^2 * sum y0[src]   (fp16 out)
// LAYER=1: bufB = sum bufA[src]               (fp32 out; dinv[dst] dropped by l2norm)
template <int LAYER>
__global__ __launch_bounds__(256)
void lgconv3_kernel() {
    int k    = blockIdx.y;
    const uint4* __restrict__ xin = (LAYER == 0)
        ? reinterpret_cast<const uint4*>(g_y0[k])
        : reinterpret_cast<const uint4*>(g_bufA[k]);
    int w    = (blockIdx.x * blockDim.x + threadIdx.x) >> 5;
    int lane = threadIdx.x & 31;
    if (w >= NUM_NODES) return;
    int g = lane >> 3;      // edge slot within batch (0..3)
    int i = lane & 7;       // 16B chunk within row (0..7)
    const unsigned short* __restrict__ row = &g_bkt[k][(size_t)w * CAP];
    int n = g_cnt[k][w];
    if (n > CAP) n = CAP;

    __half2 zero = __float2half2_rn(0.0f);
    __half2 accA[4] = {zero, zero, zero, zero};
    __half2 accB[4] = {zero, zero, zero, zero};

    int j = 0;
    // 8 edges per iteration: 2 independent LDG.128 per lane
    for (; j + 8 <= n; j += 8) {
        uint4 s8 = *reinterpret_cast<const uint4*>(row + j);   // 8 src ids, broadcast
        unsigned src0 = src_from_words(s8.x, s8.y, g);
        unsigned src1 = src_from_words(s8.z, s8.w, g);
        uint4 v0 = __ldg(xin + (size_t)src0 * ROWU4 + i);
        uint4 v1 = __ldg(xin + (size_t)src1 * ROWU4 + i);
        hacc(accA, v0);
        hacc(accB, v1);
    }
    if (j + 4 <= n) {
        uint2 s4 = *reinterpret_cast<const uint2*>(row + j);
        unsigned src = src_from_words(s4.x, s4.y, g);
        uint4 v = __ldg(xin + (size_t)src * ROWU4 + i);
        hacc(accA, v);
        j += 4;
    }
    int rem = n - j;   // 0..3
    if (g < rem) {
        unsigned src = row[j + g];
        uint4 v = __ldg(xin + (size_t)src * ROWU4 + i);
        hacc(accB, v);
    }

    // fp32 totals for the 8 features this lane owns, then reduce across groups
    float s[8];
    #pragma unroll
    for (int t = 0; t < 4; t++) {
        float2 fa = __half22float2(accA[t]);
        float2 fb = __half22float2(accB[t]);
        s[2 * t]     = fa.x + fb.x;
        s[2 * t + 1] = fa.y + fb.y;
    }
    #pragma unroll
    for (int t = 0; t < 8; t++) {
        s[t] += __shfl_xor_sync(0xffffffffu, s[t], 8);
        s[t] += __shfl_xor_sync(0xffffffffu, s[t], 16);
    }

    if (g == 0) {   // lanes 0..7 write the row
        if (LAYER == 0) {
            float dv  = g_dinv[k][w];
            float dv2 = dv * dv;
            uint4 o;
            *reinterpret_cast<__half2*>(&o.x) = __floats2half2_rn(s[0] * dv2, s[1] * dv2);
            *reinterpret_cast<__half2*>(&o.y) = __floats2half2_rn(s[2] * dv2, s[3] * dv2);
            *reinterpret_cast<__half2*>(&o.z) = __floats2half2_rn(s[4] * dv2, s[5] * dv2);
            *reinterpret_cast<__half2*>(&o.w) = __floats2half2_rn(s[6] * dv2, s[7] * dv2);
            reinterpret_cast<uint4*>(g_bufA[k])[(size_t)w * ROWU4 + i] = o;
        } else {
            float* op = g_bufB[k] + (size_t)w * DIM + i * 8;
            *reinterpret_cast<float4*>(op)     = make_float4(s[0], s[1], s[2], s[3]);
            *reinterpret_cast<float4*>(op + 4) = make_float4(s[4], s[5], s[6], s[7]);
        }
    }
}

// out = sum_k w_k * l2norm(g_bufB[k]); w from softmax(alpha)+clip+renorm
__global__ __launch_bounds__(256)
void combine3_kernel(const float* __restrict__ alpha, float* __restrict__ out) {
    int w    = (blockIdx.x * blockDim.x + threadIdx.x) >> 5;
    int lane = threadIdx.x & 31;
    if (w >= NUM_NODES) return;
    float a0 = __ldg(alpha), a1 = __ldg(alpha + 1), a2 = __ldg(alpha + 2);
    float m  = fmaxf(a0, fmaxf(a1, a2));
    float e0 = expf(a0 - m), e1 = expf(a1 - m), e2 = expf(a2 - m);
    float es = e0 + e1 + e2;
    float w0 = fmaxf(e0 / es, 1e-4f);
    float w1 = fmaxf(e1 / es, 1e-4f);
    float w2 = fmaxf(e2 / es, 1e-4f);
    float wsum = w0 + w1 + w2;
    w0 /= wsum; w1 /= wsum; w2 /= wsum;

    size_t off = (size_t)w * DIM + lane * 2;
    float2 v0 = *reinterpret_cast<const float2*>(g_bufB[0] + off);
    float2 v1 = *reinterpret_cast<const float2*>(g_bufB[1] + off);
    float2 v2 = *reinterpret_cast<const float2*>(g_bufB[2] + off);

    float s0 = v0.x * v0.x + v0.y * v0.y;
    float s1 = v1.x * v1.x + v1.y * v1.y;
    float s2 = v2.x * v2.x + v2.y * v2.y;
    #pragma unroll
    for (int o = 16; o; o >>= 1) {
        s0 += __shfl_xor_sync(0xffffffffu, s0, o);
        s1 += __shfl_xor_sync(0xffffffffu, s1, o);
        s2 += __shfl_xor_sync(0xffffffffu, s2, o);
    }
    float c0 = w0 / fmaxf(sqrtf(s0), EPSN);
    float c1 = w1 / fmaxf(sqrtf(s1), EPSN);
    float c2 = w2 / fmaxf(sqrtf(s2), EPSN);
    float2 r = make_float2(c0 * v0.x + c1 * v1.x + c2 * v2.x,
                           c0 * v0.y + c1 * v1.y + c2 * v2.y);
    *reinterpret_cast<float2*>(out + off) = r;
}

// ---------------- launch ----------------
extern "C" void kernel_launch(void* const* d_in, const int* in_sizes, int n_in,
                              void* d_out, int out_size) {
    const float* x     = (const float*)d_in[0];
    const float* alpha = (const float*)d_in[1];
    const int* ei0 = (const int*)d_in[2];
    const int* ei1 = (const int*)d_in[3];
    const int* ei2 = (const int*)d_in[4];
    float* out = (float*)d_out;

    const int TB = 256;
    dim3 gNodeWarp((NUM_NODES * 32 + TB - 1) / TB, 3);
    dim3 gEdge((NUM_EDGES + TB - 1) / TB, 3);
    int  gNode1     = (NUM_NODES + TB - 1) / TB;
    int  gNodeWarp1 = (NUM_NODES * 32 + TB - 1) / TB;

    zero3_kernel<<<gNode1, TB>>>();
    bucket3_kernel<<<gEdge, TB>>>(ei0, ei1, ei2);
    norm_scale3_kernel<<<gNodeWarp1, TB>>>(x);
    lgconv3_kernel<0><<<gNodeWarp, TB>>>();
    lgconv3_kernel<1><<<gNodeWarp, TB>>>();
    combine3_kernel<<<gNodeWarp1, TB>>>(alpha, out);
}

// round 8
// speedup vs baseline: 1.0127x; 1.0127x over previous
#include <cuda_runtime.h>
#include <cuda_fp16.h>
#include <math.h>

#define NUM_NODES 50000
#define DIM       64
#define DIM2      32            // half2 per feature row
#define NUM_EDGES 800000
#define CAP       128           // bucket capacity per destination node
#define EPSN      1e-12f

// ---------------- scratch (static device globals; device-code refs only) ----------------
__device__ __half2  g_y0  [3][NUM_NODES * DIM2];   // dinv_k * l2norm(x), fp16
__device__ __half2  g_bufA[3][NUM_NODES * DIM2];   // layer-1 out (incl. dinv^2), fp16
__device__ float    g_bufB[3][NUM_NODES * DIM];    // layer-2 out (unscaled), fp32
__device__ int      g_cnt [3][NUM_NODES];          // degrees / append cursors
__device__ float    g_dinv[3][NUM_NODES];
__device__ unsigned short g_bkt[3][NUM_NODES * CAP]; // src indices per dst bucket

// ---------------- kernels ----------------

__global__ __launch_bounds__(256)
void zero3_kernel() {
    int i = blockIdx.x * blockDim.x + threadIdx.x;
    if (i < NUM_NODES) { g_cnt[0][i] = 0; g_cnt[1][i] = 0; g_cnt[2][i] = 0; }
}

// single-pass bucket scatter: degree counts AND per-dst edge lists
__global__ __launch_bounds__(256)
void bucket3_kernel(const int* __restrict__ ei0, const int* __restrict__ ei1,
                    const int* __restrict__ ei2) {
    int e = blockIdx.x * blockDim.x + threadIdx.x;
    if (e >= NUM_EDGES) return;
    int k = blockIdx.y;
    const int* ei = (k == 0) ? ei0 : (k == 1) ? ei1 : ei2;
    int s = ei[e];
    int d = ei[e + NUM_EDGES];
    int p = atomicAdd(&g_cnt[k][d], 1);
    if (p < CAP) g_bkt[k][(size_t)d * CAP + p] = (unsigned short)s;
}

// dinv_k = cnt>0 ? rsqrt(cnt) : 0 ; y0_k = half(dinv_k * x / max(||x||,eps))
__global__ __launch_bounds__(256)
void norm_scale3_kernel(const float* __restrict__ x) {
    int w    = (blockIdx.x * blockDim.x + threadIdx.x) >> 5;
    int lane = threadIdx.x & 31;
    if (w >= NUM_NODES) return;
    const float2 v = *reinterpret_cast<const float2*>(x + (size_t)w * DIM + lane * 2);
    float sq = v.x * v.x + v.y * v.y;
    #pragma unroll
    for (int o = 16; o; o >>= 1) sq += __shfl_xor_sync(0xffffffffu, sq, o);
    float s = 1.0f / fmaxf(sqrtf(sq), EPSN);
    #pragma unroll
    for (int k = 0; k < 3; k++) {
        int   c  = g_cnt[k][w];
        float dv = (c > 0) ? rsqrtf((float)c) : 0.0f;
        if (lane == 0) g_dinv[k][w] = dv;
        float sc = s * dv;
        g_y0[k][(size_t)w * DIM2 + lane] = __floats2half2_rn(v.x * sc, v.y * sc);
    }
}

// LGConv layer, all 3 relations (gridDim.y = 3); warp per destination node.
// Coalesced layout: lane = half2 column of the gathered row (1 cache line per LDG).
// fp16 accumulation in 8 independent slots (chain depth ~deg/8), fp32 finish.
// LAYER=0: bufA = dinv[dst]^2 * sum y0[src]   (fp16 out)
// LAYER=1: bufB = sum bufA[src]               (fp32 out; dinv[dst] dropped by l2norm)
template <int LAYER>
__global__ __launch_bounds__(256)
void lgconv3_kernel() {
    int k    = blockIdx.y;
    const __half2* __restrict__ xin = (LAYER == 0) ? g_y0[k] : g_bufA[k];
    int w    = (blockIdx.x * blockDim.x + threadIdx.x) >> 5;
    int lane = threadIdx.x & 31;
    if (w >= NUM_NODES) return;
    const unsigned short* __restrict__ row = &g_bkt[k][(size_t)w * CAP];
    int n = g_cnt[k][w];
    if (n > CAP) n = CAP;

    __half2 z = __float2half2_rn(0.0f);
    __half2 a0 = z, a1 = z, a2 = z, a3 = z, a4 = z, a5 = z, a6 = z, a7 = z;

    int j = 0;
    // 8 edges per iteration: 8 independent coalesced LDG.64s, 8 fp16 acc chains
    for (; j + 8 <= n; j += 8) {
        uint4 s8 = *reinterpret_cast<const uint4*>(row + j);   // 8 src ids
        unsigned i0 = s8.x & 0xFFFFu, i1 = s8.x >> 16;
        unsigned i2 = s8.y & 0xFFFFu, i3 = s8.y >> 16;
        unsigned i4 = s8.z & 0xFFFFu, i5 = s8.z >> 16;
        unsigned i6 = s8.w & 0xFFFFu, i7 = s8.w >> 16;
        a0 = __hadd2(a0, __ldg(xin + (size_t)i0 * DIM2 + lane));
        a1 = __hadd2(a1, __ldg(xin + (size_t)i1 * DIM2 + lane));
        a2 = __hadd2(a2, __ldg(xin + (size_t)i2 * DIM2 + lane));
        a3 = __hadd2(a3, __ldg(xin + (size_t)i3 * DIM2 + lane));
        a4 = __hadd2(a4, __ldg(xin + (size_t)i4 * DIM2 + lane));
        a5 = __hadd2(a5, __ldg(xin + (size_t)i5 * DIM2 + lane));
        a6 = __hadd2(a6, __ldg(xin + (size_t)i6 * DIM2 + lane));
        a7 = __hadd2(a7, __ldg(xin + (size_t)i7 * DIM2 + lane));
    }
    if (j + 4 <= n) {
        uint2 s4 = *reinterpret_cast<const uint2*>(row + j);
        unsigned i0 = s4.x & 0xFFFFu, i1 = s4.x >> 16;
        unsigned i2 = s4.y & 0xFFFFu, i3 = s4.y >> 16;
        a0 = __hadd2(a0, __ldg(xin + (size_t)i0 * DIM2 + lane));
        a1 = __hadd2(a1, __ldg(xin + (size_t)i1 * DIM2 + lane));
        a2 = __hadd2(a2, __ldg(xin + (size_t)i2 * DIM2 + lane));
        a3 = __hadd2(a3, __ldg(xin + (size_t)i3 * DIM2 + lane));
        j += 4;
    }
    // tail 0..3 into distinct slots (keeps chains short)
    if (j < n)     a4 = __hadd2(a4, __ldg(xin + (size_t)row[j]     * DIM2 + lane));
    if (j + 1 < n) a5 = __hadd2(a5, __ldg(xin + (size_t)row[j + 1] * DIM2 + lane));
    if (j + 2 < n) a6 = __hadd2(a6, __ldg(xin + (size_t)row[j + 2] * DIM2 + lane));

    // fp32 finish (pairwise)
    float2 f0 = __half22float2(a0), f1 = __half22float2(a1);
    float2 f2 = __half22float2(a2), f3 = __half22float2(a3);
    float2 f4 = __half22float2(a4), f5 = __half22float2(a5);
    float2 f6 = __half22float2(a6), f7 = __half22float2(a7);
    float ax = ((f0.x + f1.x) + (f2.x + f3.x)) + ((f4.x + f5.x) + (f6.x + f7.x));
    float ay = ((f0.y + f1.y) + (f2.y + f3.y)) + ((f4.y + f5.y) + (f6.y + f7.y));

    if (LAYER == 0) {
        float dv  = g_dinv[k][w];
        float dv2 = dv * dv;
        g_bufA[k][(size_t)w * DIM2 + lane] = __floats2half2_rn(ax * dv2, ay * dv2);
    } else {
        *reinterpret_cast<float2*>(g_bufB[k] + (size_t)w * DIM + lane * 2) =
            make_float2(ax, ay);
    }
}

// out = sum_k w_k * l2norm(g_bufB[k]); w from softmax(alpha)+clip+renorm
__global__ __launch_bounds__(256)
void combine3_kernel(const float* __restrict__ alpha, float* __restrict__ out) {
    int w    = (blockIdx.x * blockDim.x + threadIdx.x) >> 5;
    int lane = threadIdx.x & 31;
    if (w >= NUM_NODES) return;
    float a0 = __ldg(alpha), a1 = __ldg(alpha + 1), a2 = __ldg(alpha + 2);
    float m  = fmaxf(a0, fmaxf(a1, a2));
    float e0 = expf(a0 - m), e1 = expf(a1 - m), e2 = expf(a2 - m);
    float es = e0 + e1 + e2;
    float w0 = fmaxf(e0 / es, 1e-4f);
    float w1 = fmaxf(e1 / es, 1e-4f);
    float w2 = fmaxf(e2 / es, 1e-4f);
    float wsum = w0 + w1 + w2;
    w0 /= wsum; w1 /= wsum; w2 /= wsum;

    size_t off = (size_t)w * DIM + lane * 2;
    float2 v0 = *reinterpret_cast<const float2*>(g_bufB[0] + off);
    float2 v1 = *reinterpret_cast<const float2*>(g_bufB[1] + off);
    float2 v2 = *reinterpret_cast<const float2*>(g_bufB[2] + off);

    float s0 = v0.x * v0.x + v0.y * v0.y;
    float s1 = v1.x * v1.x + v1.y * v1.y;
    float s2 = v2.x * v2.x + v2.y * v2.y;
    #pragma unroll
    for (int o = 16; o; o >>= 1) {
        s0 += __shfl_xor_sync(0xffffffffu, s0, o);
        s1 += __shfl_xor_sync(0xffffffffu, s1, o);
        s2 += __shfl_xor_sync(0xffffffffu, s2, o);
    }
    float c0 = w0 / fmaxf(sqrtf(s0), EPSN);
    float c1 = w1 / fmaxf(sqrtf(s1), EPSN);
    float c2 = w2 / fmaxf(sqrtf(s2), EPSN);
    float2 r = make_float2(c0 * v0.x + c1 * v1.x + c2 * v2.x,
                           c0 * v0.y + c1 * v1.y + c2 * v2.y);
    *reinterpret_cast<float2*>(out + off) = r;
}

// ---------------- launch ----------------
extern "C" void kernel_launch(void* const* d_in, const int* in_sizes, int n_in,
                              void* d_out, int out_size) {
    const float* x     = (const float*)d_in[0];
    const float* alpha = (const float*)d_in[1];
    const int* ei0 = (const int*)d_in[2];
    const int* ei1 = (const int*)d_in[3];
    const int* ei2 = (const int*)d_in[4];
    float* out = (float*)d_out;

    const int TB = 256;
    dim3 gNodeWarp((NUM_NODES * 32 + TB - 1) / TB, 3);
    dim3 gEdge((NUM_EDGES + TB - 1) / TB, 3);
    int  gNode1     = (NUM_NODES + TB - 1) / TB;
    int  gNodeWarp1 = (NUM_NODES * 32 + TB - 1) / TB;

    zero3_kernel<<<gNode1, TB>>>();
    bucket3_kernel<<<gEdge, TB>>>(ei0, ei1, ei2);
    norm_scale3_kernel<<<gNodeWarp1, TB>>>(x);
    lgconv3_kernel<0><<<gNodeWarp, TB>>>();
    lgconv3_kernel<1><<<gNodeWarp, TB>>>();
    combine3_kernel<<<gNodeWarp1, TB>>>(alpha, out);
}

// round 9
// speedup vs baseline: 1.1630x; 1.1484x over previous
#include <cuda_runtime.h>
#include <cuda_fp16.h>
#include <math.h>

#define NUM_NODES 50000
#define DIM       64
#define DIM2      32            // half2 per feature row
#define ROWU2     16            // uint2 (8B) chunks per 128B row
#define NUM_EDGES 800000
#define CAP       128           // bucket capacity per destination node
#define EPSN      1e-12f

// ---------------- scratch (static device globals; device-code refs only) ----------------
__device__ __half2  g_y0  [3][NUM_NODES * DIM2];   // dinv_k * l2norm(x), fp16
__device__ __half2  g_bufA[3][NUM_NODES * DIM2];   // layer-1 out (incl. dinv^2), fp16
__device__ int      g_cnt [3][NUM_NODES];          // degrees / append cursors
__device__ float    g_dinv[3][NUM_NODES];
__device__ unsigned short g_bkt[3][NUM_NODES * CAP]; // src indices per dst bucket

// ---------------- kernels ----------------

__global__ __launch_bounds__(256)
void zero3_kernel() {
    int i = blockIdx.x * blockDim.x + threadIdx.x;
    if (i < NUM_NODES) { g_cnt[0][i] = 0; g_cnt[1][i] = 0; g_cnt[2][i] = 0; }
}

// single-pass bucket scatter: degree counts AND per-dst edge lists
__global__ __launch_bounds__(256)
void bucket3_kernel(const int* __restrict__ ei0, const int* __restrict__ ei1,
                    const int* __restrict__ ei2) {
    int e = blockIdx.x * blockDim.x + threadIdx.x;
    if (e >= NUM_EDGES) return;
    int k = blockIdx.y;
    const int* ei = (k == 0) ? ei0 : (k == 1) ? ei1 : ei2;
    int s = ei[e];
    int d = ei[e + NUM_EDGES];
    int p = atomicAdd(&g_cnt[k][d], 1);
    if (p < CAP) g_bkt[k][(size_t)d * CAP + p] = (unsigned short)s;
}

// dinv_k = cnt>0 ? rsqrt(cnt) : 0 ; y0_k = half(dinv_k * x / max(||x||,eps))
__global__ __launch_bounds__(256)
void norm_scale3_kernel(const float* __restrict__ x) {
    int w    = (blockIdx.x * blockDim.x + threadIdx.x) >> 5;
    int lane = threadIdx.x & 31;
    if (w >= NUM_NODES) return;
    const float2 v = *reinterpret_cast<const float2*>(x + (size_t)w * DIM + lane * 2);
    float sq = v.x * v.x + v.y * v.y;
    #pragma unroll
    for (int o = 16; o; o >>= 1) sq += __shfl_xor_sync(0xffffffffu, sq, o);
    float s = 1.0f / fmaxf(sqrtf(sq), EPSN);
    #pragma unroll
    for (int k = 0; k < 3; k++) {
        int   c  = g_cnt[k][w];
        float dv = (c > 0) ? rsqrtf((float)c) : 0.0f;
        if (lane == 0) g_dinv[k][w] = dv;
        float sc = s * dv;
        g_y0[k][(size_t)w * DIM2 + lane] = __floats2half2_rn(v.x * sc, v.y * sc);
    }
}

// Half-warp-per-edge gather over one bucket row.
// h = lane>>4 selects which edge of a pair; xbase is already offset by the lane's
// 8B column chunk c. Returns this lane's 4-column fp32 partial sums (own half only).
__device__ __forceinline__ float4 gather_row(const uint2* __restrict__ xbase,
                                             const unsigned short* __restrict__ row,
                                             int n, unsigned h) {
    __half2 z = __float2half2_rn(0.0f);
    __half2 a0l = z, a0h = z, a1l = z, a1h = z;
    __half2 a2l = z, a2h = z, a3l = z, a3h = z;
    unsigned sh = h << 4;   // 0 or 16

    int j = 0;
    for (; j + 8 <= n; j += 8) {      // 8 edges per iter: 4 per half
        uint4 s8 = *reinterpret_cast<const uint4*>(row + j);
        unsigned i0 = (s8.x >> sh) & 0xFFFFu;
        unsigned i1 = (s8.y >> sh) & 0xFFFFu;
        unsigned i2 = (s8.z >> sh) & 0xFFFFu;
        unsigned i3 = (s8.w >> sh) & 0xFFFFu;
        uint2 v0 = __ldg(xbase + (size_t)i0 * ROWU2);
        uint2 v1 = __ldg(xbase + (size_t)i1 * ROWU2);
        uint2 v2 = __ldg(xbase + (size_t)i2 * ROWU2);
        uint2 v3 = __ldg(xbase + (size_t)i3 * ROWU2);
        a0l = __hadd2(a0l, *reinterpret_cast<__half2*>(&v0.x));
        a0h = __hadd2(a0h, *reinterpret_cast<__half2*>(&v0.y));
        a1l = __hadd2(a1l, *reinterpret_cast<__half2*>(&v1.x));
        a1h = __hadd2(a1h, *reinterpret_cast<__half2*>(&v1.y));
        a2l = __hadd2(a2l, *reinterpret_cast<__half2*>(&v2.x));
        a2h = __hadd2(a2h, *reinterpret_cast<__half2*>(&v2.y));
        a3l = __hadd2(a3l, *reinterpret_cast<__half2*>(&v3.x));
        a3h = __hadd2(a3h, *reinterpret_cast<__half2*>(&v3.y));
    }
    if (j < n) {                      // masked tail (reads of row are within CAP)
        uint4 s8 = *reinterpret_cast<const uint4*>(row + j);
        unsigned wrd[4] = { s8.x, s8.y, s8.z, s8.w };
        #pragma unroll
        for (int t = 0; t < 4; t++) {
            int e = j + 2 * t + (int)h;
            unsigned idx = (wrd[t] >> sh) & 0xFFFFu;
            if (e < n) {
                uint2 v = __ldg(xbase + (size_t)idx * ROWU2);
                switch (t) {
                    case 0: a0l = __hadd2(a0l, *reinterpret_cast<__half2*>(&v.x));
                            a0h = __hadd2(a0h, *reinterpret_cast<__half2*>(&v.y)); break;
                    case 1: a1l = __hadd2(a1l, *reinterpret_cast<__half2*>(&v.x));
                            a1h = __hadd2(a1h, *reinterpret_cast<__half2*>(&v.y)); break;
                    case 2: a2l = __hadd2(a2l, *reinterpret_cast<__half2*>(&v.x));
                            a2h = __hadd2(a2h, *reinterpret_cast<__half2*>(&v.y)); break;
                    default:a3l = __hadd2(a3l, *reinterpret_cast<__half2*>(&v.x));
                            a3h = __hadd2(a3h, *reinterpret_cast<__half2*>(&v.y)); break;
                }
            }
        }
    }
    float2 f0l = __half22float2(a0l), f1l = __half22float2(a1l);
    float2 f2l = __half22float2(a2l), f3l = __half22float2(a3l);
    float2 f0h = __half22float2(a0h), f1h = __half22float2(a1h);
    float2 f2h = __half22float2(a2h), f3h = __half22float2(a3h);
    float4 s;
    s.x = (f0l.x + f1l.x) + (f2l.x + f3l.x);
    s.y = (f0l.y + f1l.y) + (f2l.y + f3l.y);
    s.z = (f0h.x + f1h.x) + (f2h.x + f3h.x);
    s.w = (f0h.y + f1h.y) + (f2h.y + f3h.y);
    return s;
}

// Layer 1, all 3 relations (gridDim.y = 3): bufA = dinv[dst]^2 * sum y0[src], fp16 out.
__global__ __launch_bounds__(256)
void lgconv0_kernel() {
    int k    = blockIdx.y;
    int w    = (blockIdx.x * blockDim.x + threadIdx.x) >> 5;
    int lane = threadIdx.x & 31;
    if (w >= NUM_NODES) return;
    unsigned h = (unsigned)(lane >> 4);
    int      c = lane & 15;
    const uint2* xbase = reinterpret_cast<const uint2*>(g_y0[k]) + c;
    const unsigned short* row = &g_bkt[k][(size_t)w * CAP];
    int n = g_cnt[k][w];
    if (n > CAP) n = CAP;

    float4 s = gather_row(xbase, row, n, h);
    s.x += __shfl_xor_sync(0xffffffffu, s.x, 16);
    s.y += __shfl_xor_sync(0xffffffffu, s.y, 16);
    s.z += __shfl_xor_sync(0xffffffffu, s.z, 16);
    s.w += __shfl_xor_sync(0xffffffffu, s.w, 16);

    if (h == 0) {
        float dv  = g_dinv[k][w];
        float dv2 = dv * dv;
        uint2 o;
        *reinterpret_cast<__half2*>(&o.x) = __floats2half2_rn(s.x * dv2, s.y * dv2);
        *reinterpret_cast<__half2*>(&o.y) = __floats2half2_rn(s.z * dv2, s.w * dv2);
        reinterpret_cast<uint2*>(g_bufA[k])[(size_t)w * ROWU2 + c] = o;
    }
}

// Layer 2 + combine, fused: one warp per node handles all 3 relations.
// out = sum_k w_k * l2norm(sum_src bufA[k][src])   (dinv[dst] dropped by l2norm)
__global__ __launch_bounds__(256)
void lgconv1_combine_kernel(const float* __restrict__ alpha, float* __restrict__ out) {
    int w    = (blockIdx.x * blockDim.x + threadIdx.x) >> 5;
    int lane = threadIdx.x & 31;
    if (w >= NUM_NODES) return;
    unsigned h = (unsigned)(lane >> 4);
    int      c = lane & 15;

    // softmax(alpha) + clip + renorm (broadcast loads)
    float a0 = __ldg(alpha), a1 = __ldg(alpha + 1), a2 = __ldg(alpha + 2);
    float m  = fmaxf(a0, fmaxf(a1, a2));
    float e0 = expf(a0 - m), e1 = expf(a1 - m), e2 = expf(a2 - m);
    float es = e0 + e1 + e2;
    float wk[3];
    wk[0] = fmaxf(e0 / es, 1e-4f);
    wk[1] = fmaxf(e1 / es, 1e-4f);
    wk[2] = fmaxf(e2 / es, 1e-4f);
    float wsum = wk[0] + wk[1] + wk[2];

    float4 acc = make_float4(0.f, 0.f, 0.f, 0.f);
    #pragma unroll
    for (int k = 0; k < 3; k++) {
        const uint2* xbase = reinterpret_cast<const uint2*>(g_bufA[k]) + c;
        const unsigned short* row = &g_bkt[k][(size_t)w * CAP];
        int n = g_cnt[k][w];
        if (n > CAP) n = CAP;

        float4 s = gather_row(xbase, row, n, h);
        s.x += __shfl_xor_sync(0xffffffffu, s.x, 16);
        s.y += __shfl_xor_sync(0xffffffffu, s.y, 16);
        s.z += __shfl_xor_sync(0xffffffffu, s.z, 16);
        s.w += __shfl_xor_sync(0xffffffffu, s.w, 16);

        float ssq = s.x * s.x + s.y * s.y + s.z * s.z + s.w * s.w;
        #pragma unroll
        for (int o = 8; o; o >>= 1) ssq += __shfl_xor_sync(0xffffffffu, ssq, o);

        float ck = (wk[k] / wsum) / fmaxf(sqrtf(ssq), EPSN);
        acc.x += ck * s.x;
        acc.y += ck * s.y;
        acc.z += ck * s.z;
        acc.w += ck * s.w;
    }
    if (h == 0)
        *reinterpret_cast<float4*>(out + (size_t)w * DIM + c * 4) = acc;
}

// ---------------- launch ----------------
extern "C" void kernel_launch(void* const* d_in, const int* in_sizes, int n_in,
                              void* d_out, int out_size) {
    const float* x     = (const float*)d_in[0];
    const float* alpha = (const float*)d_in[1];
    const int* ei0 = (const int*)d_in[2];
    const int* ei1 = (const int*)d_in[3];
    const int* ei2 = (const int*)d_in[4];
    float* out = (float*)d_out;

    const int TB = 256;
    dim3 gNodeWarp3((NUM_NODES * 32 + TB - 1) / TB, 3);
    dim3 gEdge((NUM_EDGES + TB - 1) / TB, 3);
    int  gNode1     = (NUM_NODES + TB - 1) / TB;
    int  gNodeWarp1 = (NUM_NODES * 32 + TB - 1) / TB;

    zero3_kernel<<<gNode1, TB>>>();
    bucket3_kernel<<<gEdge, TB>>>(ei0, ei1, ei2);
    norm_scale3_kernel<<<gNodeWarp1, TB>>>(x);
    lgconv0_kernel<<<gNodeWarp3, TB>>>();
    lgconv1_combine_kernel<<<gNodeWarp1, TB>>>(alpha, out);
}